// round 4
// baseline (speedup 1.0000x reference)
#include <cuda_runtime.h>
#include <cuda_bf16.h>
#include <cstdint>

// ============================================================================
// Problem constants
// ============================================================================
#define BDIM 4
#define TDIM 4096
#define DDIM 2048
#define MROWS (BDIM * TDIM)        // 16384 rows of x
#define EDIM  (3 * DDIM)           // 6144 output features of qkv
#define KDIM  DDIM                 // 2048 reduction dim
#define EPSF  1.1920929e-07f       // finfo(float32).eps

// GEMM tiling (mma.sync path — tcgen05 is rejected by the harness's
// compute_103 virtual-arch PTX stage)
#define TM 128
#define TN 128
#define TK 64                      // K-chunk (64 bf16 = 128B rows, SW128)
#define NKC (KDIM / TK)            // 32 chunks
#define GEMM_THREADS 256
#define STAGE_BYTES (4 * 128 * 128)   // 4 tiles x 16KB = 64KB per stage
#define TILE_BYTES  (128 * 128)       // 16KB per [128 x 64 bf16] tile

// ============================================================================
// Scratch (static device globals — allocation-free rule)
// ============================================================================
__device__ __nv_bfloat16 g_nhi[MROWS * DDIM];
__device__ __nv_bfloat16 g_nlo[MROWS * DDIM];
__device__ __nv_bfloat16 g_whi[EDIM * DDIM];
__device__ __nv_bfloat16 g_wlo[EDIM * DDIM];
__device__ float g_qkv[(size_t)MROWS * EDIM];   // 402 MB fp32
__device__ float g_sq[MROWS * DDIM];            // sigmoid(rmsnorm(q))
__device__ float g_ww[MROWS * DDIM];            // exp(rmsnorm(k))
__device__ float g_kv[MROWS * DDIM];            // w * v
__device__ float g_pw[32 * 8192];               // chunk partials (w)
__device__ float g_pkv[32 * 8192];              // chunk partials (kv)

// ============================================================================
// Helpers
// ============================================================================
__device__ __forceinline__ uint32_t smem_u32(const void* p) {
    uint32_t a;
    asm("{ .reg .u64 t; cvta.to.shared.u64 t, %1; cvt.u32.u64 %0, t; }" : "=r"(a) : "l"(p));
    return a;
}

#define SMEM_SWIZZLE_128B(off) ((off) ^ (((off) >> 3) & 0x70))

__device__ __forceinline__ void cp_async16(uint32_t dst, const void* src) {
    asm volatile("cp.async.cg.shared.global [%0], [%1], 16;" :: "r"(dst), "l"(src));
}
__device__ __forceinline__ void cp_commit() {
    asm volatile("cp.async.commit_group;" ::: "memory");
}
__device__ __forceinline__ void cp_wait1() {
    asm volatile("cp.async.wait_group 1;" ::: "memory");
}
__device__ __forceinline__ void cp_wait0() {
    asm volatile("cp.async.wait_group 0;" ::: "memory");
}

__device__ __forceinline__ void ldmx4(uint32_t* r, uint32_t addr) {
    asm volatile("ldmatrix.sync.aligned.m8n8.x4.shared.b16 {%0,%1,%2,%3}, [%4];"
                 : "=r"(r[0]), "=r"(r[1]), "=r"(r[2]), "=r"(r[3]) : "r"(addr));
}

__device__ __forceinline__ void mma16816(float* c, const uint32_t* a, const uint32_t* b) {
    asm volatile(
        "mma.sync.aligned.m16n8k16.row.col.f32.bf16.bf16.f32 "
        "{%0,%1,%2,%3}, {%4,%5,%6,%7}, {%8,%9}, {%0,%1,%2,%3};"
        : "+f"(c[0]), "+f"(c[1]), "+f"(c[2]), "+f"(c[3])
        : "r"(a[0]), "r"(a[1]), "r"(a[2]), "r"(a[3]), "r"(b[0]), "r"(b[1]));
}

// ============================================================================
// Block reduce (two values at once; safe for repeated calls)
// ============================================================================
__device__ __forceinline__ void blockReduce2(float& a, float& b) {
    __shared__ float sa[8], sb[8];
    int tid = threadIdx.x, wid = tid >> 5, lid = tid & 31;
    #pragma unroll
    for (int o = 16; o > 0; o >>= 1) {
        a += __shfl_xor_sync(0xffffffffu, a, o);
        b += __shfl_xor_sync(0xffffffffu, b, o);
    }
    if (lid == 0) { sa[wid] = a; sb[wid] = b; }
    __syncthreads();
    if (tid < 32) {
        a = (lid < 8) ? sa[lid] : 0.f;
        b = (lid < 8) ? sb[lid] : 0.f;
        #pragma unroll
        for (int o = 4; o > 0; o >>= 1) {
            a += __shfl_xor_sync(0xffffffffu, a, o);
            b += __shfl_xor_sync(0xffffffffu, b, o);
        }
        if (lid == 0) { sa[0] = a; sb[0] = b; }
    }
    __syncthreads();
    a = sa[0]; b = sb[0];
    __syncthreads();
}

// ============================================================================
// Kernel 0: split W into bf16 hi/lo
// ============================================================================
__global__ void __launch_bounds__(256) k_split_w(const float* __restrict__ w) {
    int idx = blockIdx.x * 256 + threadIdx.x;
    const int n = EDIM * DDIM;
    #pragma unroll 4
    for (int i = idx; i < n; i += gridDim.x * 256) {
        float v = w[i];
        __nv_bfloat16 h = __float2bfloat16(v);
        g_whi[i] = h;
        g_wlo[i] = __float2bfloat16(v - __bfloat162float(h));
    }
}

// ============================================================================
// Kernel 1: rmsnorm(x) -> bf16 hi/lo; also copy x into out[0]
// ============================================================================
__global__ void __launch_bounds__(256) k_rms_x(const float* __restrict__ x,
                                               float* __restrict__ outx) {
    int row = blockIdx.x, tid = threadIdx.x;
    const float* xr = x + (size_t)row * DDIM;
    float v[8];
    float s = 0.f, dummy = 0.f;
    #pragma unroll
    for (int i = 0; i < 8; ++i) {
        v[i] = xr[i * 256 + tid];
        s += v[i] * v[i];
    }
    blockReduce2(s, dummy);
    float r = rsqrtf(s * (1.0f / DDIM) + EPSF);
    size_t ob = (size_t)row * DDIM;
    #pragma unroll
    for (int i = 0; i < 8; ++i) {
        int c = i * 256 + tid;
        outx[ob + c] = v[i];
        float n = v[i] * r;
        __nv_bfloat16 h = __float2bfloat16(n);
        g_nhi[ob + c] = h;
        g_nlo[ob + c] = __float2bfloat16(n - __bfloat162float(h));
    }
}

// ============================================================================
// Kernel 2: QKV GEMM via mma.sync bf16 3-way split (hi*hi + hi*lo + lo*hi)
// C[m, e] = sum_d N[m, d] * W[e, d]   (both K-major -> D = A @ B^T)
// CTA tile 128x128, K-chunk 64, double-buffered cp.async, 8 warps (4M x 2N),
// warp tile 32x64. SW128-swizzled SMEM -> conflict-free ldmatrix + cp.async.
// ============================================================================
__device__ __forceinline__ void gemm_load_chunk(uint32_t sb_stage, int m0, int n0,
                                                int kc, int tid) {
    const int k0 = kc * TK;
    #pragma unroll
    for (int i = 0; i < 16; ++i) {
        const int tile = i >> 2;                       // 0:Ah 1:Al 2:Bh 3:Bl
        const int rem = (i & 3) * 256 + tid;           // 0..1023
        const int r = rem >> 3;                        // row 0..127
        const int v = tid & 7;                         // 16B vector 0..7
        uint32_t dst = sb_stage + tile * TILE_BYTES +
                       SMEM_SWIZZLE_128B((uint32_t)(r * 128 + v * 16));
        const __nv_bfloat16* src;
        if (tile == 0)      src = g_nhi + (size_t)(m0 + r) * KDIM + k0 + v * 8;
        else if (tile == 1) src = g_nlo + (size_t)(m0 + r) * KDIM + k0 + v * 8;
        else if (tile == 2) src = g_whi + (size_t)(n0 + r) * KDIM + k0 + v * 8;
        else                src = g_wlo + (size_t)(n0 + r) * KDIM + k0 + v * 8;
        cp_async16(dst, src);
    }
}

__global__ void __launch_bounds__(GEMM_THREADS, 1) k_gemm() {
    extern __shared__ char smem[];
    const uint32_t sb = smem_u32(smem);
    const int tid = threadIdx.x;
    const int wid = tid >> 5, lane = tid & 31;
    const int warpM = wid & 3;          // 4 warps over M
    const int warpN = wid >> 2;         // 2 warps over N
    const int n0 = blockIdx.x * TN;
    const int m0 = blockIdx.y * TM;

    float c[2][8][4];
    #pragma unroll
    for (int mt = 0; mt < 2; ++mt)
        #pragma unroll
        for (int nt = 0; nt < 8; ++nt)
            #pragma unroll
            for (int j = 0; j < 4; ++j) c[mt][nt][j] = 0.f;

    gemm_load_chunk(sb, m0, n0, 0, tid);
    cp_commit();

    for (int kc = 0; kc < NKC; ++kc) {
        if (kc + 1 < NKC) {
            gemm_load_chunk(sb + ((kc + 1) & 1) * STAGE_BYTES, m0, n0, kc + 1, tid);
            cp_commit();
            cp_wait1();
        } else {
            cp_wait0();
        }
        __syncthreads();

        const uint32_t st = sb + (kc & 1) * STAGE_BYTES;
        #pragma unroll
        for (int ks = 0; ks < 4; ++ks) {
            uint32_t ah[2][4], al[2][4], bh[8][2], bl[8][2];
            // A fragments: lanes 0-15 rows, lanes>=16 take the k+8 half
            #pragma unroll
            for (int mt = 0; mt < 2; ++mt) {
                int row = warpM * 32 + mt * 16 + (lane & 15);
                int kb = ks * 32 + ((lane >> 4) << 4);
                uint32_t off = SMEM_SWIZZLE_128B((uint32_t)(row * 128 + kb));
                ldmx4(ah[mt], st + 0 * TILE_BYTES + off);
                ldmx4(al[mt], st + 1 * TILE_BYTES + off);
            }
            // B fragments: x4 covers two n8 tiles (g0 n-lo/k-lo, g1 n-lo/k-hi,
            // g2 n-hi/k-lo, g3 n-hi/k-hi)
            #pragma unroll
            for (int pt = 0; pt < 4; ++pt) {
                int row = warpN * 64 + pt * 16 + (lane & 7) + ((lane & 16) >> 1);
                int kb = ks * 32 + (((lane >> 3) & 1) << 4);
                uint32_t off = SMEM_SWIZZLE_128B((uint32_t)(row * 128 + kb));
                uint32_t rh[4], rl[4];
                ldmx4(rh, st + 2 * TILE_BYTES + off);
                ldmx4(rl, st + 3 * TILE_BYTES + off);
                bh[2 * pt][0] = rh[0]; bh[2 * pt][1] = rh[1];
                bh[2 * pt + 1][0] = rh[2]; bh[2 * pt + 1][1] = rh[3];
                bl[2 * pt][0] = rl[0]; bl[2 * pt][1] = rl[1];
                bl[2 * pt + 1][0] = rl[2]; bl[2 * pt + 1][1] = rl[3];
            }
            #pragma unroll
            for (int mt = 0; mt < 2; ++mt)
                #pragma unroll
                for (int nt = 0; nt < 8; ++nt) {
                    mma16816(c[mt][nt], ah[mt], bh[nt]);
                    mma16816(c[mt][nt], ah[mt], bl[nt]);
                    mma16816(c[mt][nt], al[mt], bh[nt]);
                }
        }
        __syncthreads();
    }

    // Epilogue: write fp32 qkv
    const int m_base = m0 + warpM * 32;
    const int n_base = n0 + warpN * 64;
    #pragma unroll
    for (int mt = 0; mt < 2; ++mt)
        #pragma unroll
        for (int nt = 0; nt < 8; ++nt) {
            int r0 = m_base + mt * 16 + (lane >> 2);
            int cc = n_base + nt * 8 + (lane & 3) * 2;
            float2 v0 = make_float2(c[mt][nt][0], c[mt][nt][1]);
            float2 v1 = make_float2(c[mt][nt][2], c[mt][nt][3]);
            *(float2*)(g_qkv + (size_t)r0 * EDIM + cc) = v0;
            *(float2*)(g_qkv + (size_t)(r0 + 8) * EDIM + cc) = v1;
        }
}

// ============================================================================
// Kernel 3: rmsnorm(q), rmsnorm(k), sigmoid(q), w=exp(k), kv=w*v
// ============================================================================
__global__ void __launch_bounds__(256) k_post() {
    int row = blockIdx.x, tid = threadIdx.x;
    const float* q = g_qkv + (size_t)row * EDIM;
    float qv[8], kk[8], vv[8];
    float sq = 0.f, sk = 0.f;
    #pragma unroll
    for (int i = 0; i < 8; ++i) {
        int c = i * 256 + tid;
        qv[i] = q[c];
        kk[i] = q[c + DDIM];
        vv[i] = q[c + 2 * DDIM];
        sq += qv[i] * qv[i];
        sk += kk[i] * kk[i];
    }
    blockReduce2(sq, sk);
    float rq = rsqrtf(sq * (1.0f / DDIM) + EPSF);
    float rk = rsqrtf(sk * (1.0f / DDIM) + EPSF);
    size_t ob = (size_t)row * DDIM;
    #pragma unroll
    for (int i = 0; i < 8; ++i) {
        int c = i * 256 + tid;
        float qn = qv[i] * rq;
        g_sq[ob + c] = 1.0f / (1.0f + expf(-qn));
        float w = expf(kk[i] * rk);
        g_ww[ob + c] = w;
        g_kv[ob + c] = w * vv[i];
    }
}

// ============================================================================
// Kernel 4a/4b/4c: chunked cumsum over T per (b, d) channel, then output
// ============================================================================
__global__ void __launch_bounds__(256) k_scan_part() {
    int gid = blockIdx.x * 256 + threadIdx.x;    // 0..262143
    int d = gid & (DDIM - 1);
    int rest = gid >> 11;
    int b = rest & 3;
    int j = rest >> 2;                           // chunk 0..31
    size_t base = ((size_t)(b * TDIM + j * 128)) * DDIM + d;
    float sw = 0.f, skv = 0.f;
    #pragma unroll 4
    for (int t = 0; t < 128; ++t) {
        sw  += g_ww[base + (size_t)t * DDIM];
        skv += g_kv[base + (size_t)t * DDIM];
    }
    int ch = b * DDIM + d;
    g_pw[j * 8192 + ch] = sw;
    g_pkv[j * 8192 + ch] = skv;
}

__global__ void __launch_bounds__(256) k_scan_ex() {
    int ch = blockIdx.x * 256 + threadIdx.x;     // 0..8191
    float rw = 0.f, rkv = 0.f;
    #pragma unroll
    for (int j = 0; j < 32; ++j) {
        int i = j * 8192 + ch;
        float tw = g_pw[i];  g_pw[i]  = rw;  rw  += tw;
        float tk = g_pkv[i]; g_pkv[i] = rkv; rkv += tk;
    }
}

__global__ void __launch_bounds__(256) k_scan_apply(float* __restrict__ out2) {
    int gid = blockIdx.x * 256 + threadIdx.x;
    int d = gid & (DDIM - 1);
    int rest = gid >> 11;
    int b = rest & 3;
    int j = rest >> 2;
    size_t base = ((size_t)(b * TDIM + j * 128)) * DDIM + d;
    int ch = b * DDIM + d;
    float rw = g_pw[j * 8192 + ch];
    float rkv = g_pkv[j * 8192 + ch];
    #pragma unroll 4
    for (int t = 0; t < 128; ++t) {
        size_t i = base + (size_t)t * DDIM;
        rw  += g_ww[i];
        rkv += g_kv[i];
        float y = rkv / (rw + 1e-6f);
        out2[i] = g_sq[i] * y;
    }
}

// ============================================================================
// Launch
// ============================================================================
extern "C" void kernel_launch(void* const* d_in, const int* in_sizes, int n_in,
                              void* d_out, int out_size) {
    const float* x  = (const float*)d_in[0];   // [4, 4096, 2048]
    const float* wq = (const float*)d_in[1];   // [6144, 2048]
    float* out = (float*)d_out;                // [2, 4, 4096, 2048]

    cudaFuncSetAttribute(k_gemm, cudaFuncAttributeMaxDynamicSharedMemorySize,
                         2 * STAGE_BYTES);

    k_split_w<<<12288, 256>>>(wq);
    k_rms_x<<<MROWS, 256>>>(x, out);
    k_gemm<<<dim3(EDIM / TN, MROWS / TM), GEMM_THREADS, 2 * STAGE_BYTES>>>();
    k_post<<<MROWS, 256>>>();
    k_scan_part<<<1024, 256>>>();
    k_scan_ex<<<32, 256>>>();
    k_scan_apply<<<1024, 256>>>(out + (size_t)MROWS * DDIM);
}

// round 5
// speedup vs baseline: 1.3104x; 1.3104x over previous
#include <cuda_runtime.h>
#include <cuda_bf16.h>
#include <cuda_fp16.h>
#include <cstdint>

// ============================================================================
// Problem constants
// ============================================================================
#define BDIM 4
#define TDIM 4096
#define DDIM 2048
#define MROWS (BDIM * TDIM)        // 16384 rows of x
#define EDIM  (3 * DDIM)           // 6144 output features of qkv
#define KDIM  DDIM                 // 2048 reduction dim
#define EPSF  1.1920929e-07f       // finfo(float32).eps

// GEMM tiling (mma.sync f16 path; 2-term split: x_h*w_h + x_h*w_l)
#define TM 128
#define TN 128
#define TK 64                      // K-chunk (64 f16 = 128B rows, SW128)
#define NKC (KDIM / TK)            // 32 chunks
#define GEMM_THREADS 512           // 16 warps: 4 over M x 4 over N, tile 32x32
#define TILE_BYTES  (128 * 128)    // 16KB per [128 x 64 f16] tile
#define STAGE_BYTES (3 * TILE_BYTES)  // Ah, Bh, Bl = 48KB per stage

// ============================================================================
// Scratch (static device globals — allocation-free rule)
// ============================================================================
__device__ __half g_nhi[MROWS * DDIM];          // fp16(rmsnorm(x))
__device__ __half g_whi[EDIM * DDIM];           // fp16 hi of W
__device__ __half g_wlo[EDIM * DDIM];           // fp16 lo of W
__device__ float g_qkv[(size_t)MROWS * EDIM];   // fp32 qkv
__device__ float g_sq[MROWS * DDIM];            // sigmoid(rmsnorm(q))
__device__ float g_ww[MROWS * DDIM];            // exp(rmsnorm(k))
__device__ float g_kv[MROWS * DDIM];            // w * v
__device__ float g_pw[32 * 8192];               // chunk partials (w)
__device__ float g_pkv[32 * 8192];              // chunk partials (kv)

// ============================================================================
// Helpers
// ============================================================================
__device__ __forceinline__ uint32_t smem_u32(const void* p) {
    uint32_t a;
    asm("{ .reg .u64 t; cvta.to.shared.u64 t, %1; cvt.u32.u64 %0, t; }" : "=r"(a) : "l"(p));
    return a;
}

#define SMEM_SWIZZLE_128B(off) ((off) ^ (((off) >> 3) & 0x70))

__device__ __forceinline__ void cp_async16(uint32_t dst, const void* src) {
    asm volatile("cp.async.cg.shared.global [%0], [%1], 16;" :: "r"(dst), "l"(src));
}
__device__ __forceinline__ void cp_commit() {
    asm volatile("cp.async.commit_group;" ::: "memory");
}
__device__ __forceinline__ void cp_wait1() {
    asm volatile("cp.async.wait_group 1;" ::: "memory");
}
__device__ __forceinline__ void cp_wait0() {
    asm volatile("cp.async.wait_group 0;" ::: "memory");
}

__device__ __forceinline__ void ldmx4(uint32_t* r, uint32_t addr) {
    asm volatile("ldmatrix.sync.aligned.m8n8.x4.shared.b16 {%0,%1,%2,%3}, [%4];"
                 : "=r"(r[0]), "=r"(r[1]), "=r"(r[2]), "=r"(r[3]) : "r"(addr));
}

__device__ __forceinline__ void mma16816(float* c, const uint32_t* a, const uint32_t* b) {
    asm volatile(
        "mma.sync.aligned.m16n8k16.row.col.f32.f16.f16.f32 "
        "{%0,%1,%2,%3}, {%4,%5,%6,%7}, {%8,%9}, {%0,%1,%2,%3};"
        : "+f"(c[0]), "+f"(c[1]), "+f"(c[2]), "+f"(c[3])
        : "r"(a[0]), "r"(a[1]), "r"(a[2]), "r"(a[3]), "r"(b[0]), "r"(b[1]));
}

// ============================================================================
// Block reduce (two values at once; safe for repeated calls)
// ============================================================================
__device__ __forceinline__ void blockReduce2(float& a, float& b) {
    __shared__ float sa[8], sb[8];
    int tid = threadIdx.x, wid = tid >> 5, lid = tid & 31;
    #pragma unroll
    for (int o = 16; o > 0; o >>= 1) {
        a += __shfl_xor_sync(0xffffffffu, a, o);
        b += __shfl_xor_sync(0xffffffffu, b, o);
    }
    if (lid == 0) { sa[wid] = a; sb[wid] = b; }
    __syncthreads();
    if (tid < 32) {
        a = (lid < 8) ? sa[lid] : 0.f;
        b = (lid < 8) ? sb[lid] : 0.f;
        #pragma unroll
        for (int o = 4; o > 0; o >>= 1) {
            a += __shfl_xor_sync(0xffffffffu, a, o);
            b += __shfl_xor_sync(0xffffffffu, b, o);
        }
        if (lid == 0) { sa[0] = a; sb[0] = b; }
    }
    __syncthreads();
    a = sa[0]; b = sb[0];
    __syncthreads();
}

// ============================================================================
// Kernel 0: split W into fp16 hi/lo
// ============================================================================
__global__ void __launch_bounds__(256) k_split_w(const float* __restrict__ w) {
    int idx = blockIdx.x * 256 + threadIdx.x;
    const int n = EDIM * DDIM;
    #pragma unroll 4
    for (int i = idx; i < n; i += gridDim.x * 256) {
        float v = w[i];
        __half h = __float2half_rn(v);
        g_whi[i] = h;
        g_wlo[i] = __float2half_rn(v - __half2float(h));
    }
}

// ============================================================================
// Kernel 1: rmsnorm(x) -> fp16; also copy x into out[0]
// ============================================================================
__global__ void __launch_bounds__(256) k_rms_x(const float* __restrict__ x,
                                               float* __restrict__ outx) {
    int row = blockIdx.x, tid = threadIdx.x;
    const float* xr = x + (size_t)row * DDIM;
    float v[8];
    float s = 0.f, dummy = 0.f;
    #pragma unroll
    for (int i = 0; i < 8; ++i) {
        v[i] = xr[i * 256 + tid];
        s += v[i] * v[i];
    }
    blockReduce2(s, dummy);
    float r = rsqrtf(s * (1.0f / DDIM) + EPSF);
    size_t ob = (size_t)row * DDIM;
    #pragma unroll
    for (int i = 0; i < 8; ++i) {
        int c = i * 256 + tid;
        outx[ob + c] = v[i];
        g_nhi[ob + c] = __float2half_rn(v[i] * r);
    }
}

// ============================================================================
// Kernel 2: QKV GEMM via mma.sync fp16 2-term split (xh*wh + xh*wl)
// C[m, e] = sum_d N[m, d] * W[e, d]   (both K-major -> D = A @ B^T)
// CTA tile 128x128, K-chunk 64, double-buffered cp.async, 16 warps (4M x 4N),
// warp tile 32x32. SW128-swizzled SMEM -> conflict-free ldmatrix + cp.async.
// ============================================================================
__device__ __forceinline__ void gemm_load_chunk(uint32_t sb_stage, int m0, int n0,
                                                int kc, int tid) {
    const int k0 = kc * TK;
    const int v = tid & 7;                              // 16B vector 0..7
    #pragma unroll
    for (int i = 0; i < 6; ++i) {
        const int tile = i >> 1;                        // 0:Ah 1:Bh 2:Bl
        const int r = (i & 1) * 64 + (tid >> 3);        // row 0..127
        uint32_t dst = sb_stage + tile * TILE_BYTES +
                       SMEM_SWIZZLE_128B((uint32_t)(r * 128 + v * 16));
        const __half* src;
        if (tile == 0)      src = g_nhi + (size_t)(m0 + r) * KDIM + k0 + v * 8;
        else if (tile == 1) src = g_whi + (size_t)(n0 + r) * KDIM + k0 + v * 8;
        else                src = g_wlo + (size_t)(n0 + r) * KDIM + k0 + v * 8;
        cp_async16(dst, src);
    }
}

__global__ void __launch_bounds__(GEMM_THREADS, 1) k_gemm() {
    extern __shared__ char smem[];
    const uint32_t sb = smem_u32(smem);
    const int tid = threadIdx.x;
    const int wid = tid >> 5, lane = tid & 31;
    const int warpM = wid & 3;          // 4 warps over M
    const int warpN = wid >> 2;         // 4 warps over N
    const int n0 = blockIdx.x * TN;
    const int m0 = blockIdx.y * TM;

    float c[2][4][4];
    #pragma unroll
    for (int mt = 0; mt < 2; ++mt)
        #pragma unroll
        for (int nt = 0; nt < 4; ++nt)
            #pragma unroll
            for (int j = 0; j < 4; ++j) c[mt][nt][j] = 0.f;

    gemm_load_chunk(sb, m0, n0, 0, tid);
    cp_commit();

    // Precomputed per-lane smem sub-offsets
    const int aRow = warpM * 32 + (lane & 15);
    const int aKb  = (lane >> 4) << 4;
    const int bRow = warpN * 32 + (lane & 7) + ((lane & 16) >> 1);
    const int bKb  = ((lane >> 3) & 1) << 4;

    for (int kc = 0; kc < NKC; ++kc) {
        if (kc + 1 < NKC) {
            gemm_load_chunk(sb + ((kc + 1) & 1) * STAGE_BYTES, m0, n0, kc + 1, tid);
            cp_commit();
            cp_wait1();
        } else {
            cp_wait0();
        }
        __syncthreads();

        const uint32_t st = sb + (kc & 1) * STAGE_BYTES;
        #pragma unroll
        for (int ks = 0; ks < 4; ++ks) {
            uint32_t ah[2][4], bh[4][2], bl[4][2];
            #pragma unroll
            for (int mt = 0; mt < 2; ++mt) {
                uint32_t off = SMEM_SWIZZLE_128B(
                    (uint32_t)((aRow + mt * 16) * 128 + ks * 32 + aKb));
                ldmx4(ah[mt], st + 0 * TILE_BYTES + off);
            }
            #pragma unroll
            for (int pt = 0; pt < 2; ++pt) {
                uint32_t off = SMEM_SWIZZLE_128B(
                    (uint32_t)((bRow + pt * 16) * 128 + ks * 32 + bKb));
                uint32_t rh[4], rl[4];
                ldmx4(rh, st + 1 * TILE_BYTES + off);
                ldmx4(rl, st + 2 * TILE_BYTES + off);
                bh[2 * pt][0] = rh[0]; bh[2 * pt][1] = rh[1];
                bh[2 * pt + 1][0] = rh[2]; bh[2 * pt + 1][1] = rh[3];
                bl[2 * pt][0] = rl[0]; bl[2 * pt][1] = rl[1];
                bl[2 * pt + 1][0] = rl[2]; bl[2 * pt + 1][1] = rl[3];
            }
            #pragma unroll
            for (int mt = 0; mt < 2; ++mt)
                #pragma unroll
                for (int nt = 0; nt < 4; ++nt) {
                    mma16816(c[mt][nt], ah[mt], bh[nt]);
                    mma16816(c[mt][nt], ah[mt], bl[nt]);
                }
        }
        __syncthreads();
    }

    // Epilogue: write fp32 qkv
    const int m_base = m0 + warpM * 32;
    const int n_base = n0 + warpN * 32;
    #pragma unroll
    for (int mt = 0; mt < 2; ++mt)
        #pragma unroll
        for (int nt = 0; nt < 4; ++nt) {
            int r0 = m_base + mt * 16 + (lane >> 2);
            int cc = n_base + nt * 8 + (lane & 3) * 2;
            float2 v0 = make_float2(c[mt][nt][0], c[mt][nt][1]);
            float2 v1 = make_float2(c[mt][nt][2], c[mt][nt][3]);
            *(float2*)(g_qkv + (size_t)r0 * EDIM + cc) = v0;
            *(float2*)(g_qkv + (size_t)(r0 + 8) * EDIM + cc) = v1;
        }
}

// ============================================================================
// Kernel 3: rmsnorm(q), rmsnorm(k), sigmoid(q), w=exp(k), kv=w*v
// ============================================================================
__global__ void __launch_bounds__(256) k_post() {
    int row = blockIdx.x, tid = threadIdx.x;
    const float* q = g_qkv + (size_t)row * EDIM;
    float qv[8], kk[8], vv[8];
    float sq = 0.f, sk = 0.f;
    #pragma unroll
    for (int i = 0; i < 8; ++i) {
        int c = i * 256 + tid;
        qv[i] = q[c];
        kk[i] = q[c + DDIM];
        vv[i] = q[c + 2 * DDIM];
        sq += qv[i] * qv[i];
        sk += kk[i] * kk[i];
    }
    blockReduce2(sq, sk);
    float rq = rsqrtf(sq * (1.0f / DDIM) + EPSF);
    float rk = rsqrtf(sk * (1.0f / DDIM) + EPSF);
    size_t ob = (size_t)row * DDIM;
    #pragma unroll
    for (int i = 0; i < 8; ++i) {
        int c = i * 256 + tid;
        float qn = qv[i] * rq;
        g_sq[ob + c] = 1.0f / (1.0f + expf(-qn));
        float w = expf(kk[i] * rk);
        g_ww[ob + c] = w;
        g_kv[ob + c] = w * vv[i];
    }
}

// ============================================================================
// Kernel 4a/4b/4c: chunked cumsum over T per (b, d) channel, then output
// ============================================================================
__global__ void __launch_bounds__(256) k_scan_part() {
    int gid = blockIdx.x * 256 + threadIdx.x;    // 0..262143
    int d = gid & (DDIM - 1);
    int rest = gid >> 11;
    int b = rest & 3;
    int j = rest >> 2;                           // chunk 0..31
    size_t base = ((size_t)(b * TDIM + j * 128)) * DDIM + d;
    float sw = 0.f, skv = 0.f;
    #pragma unroll 4
    for (int t = 0; t < 128; ++t) {
        sw  += g_ww[base + (size_t)t * DDIM];
        skv += g_kv[base + (size_t)t * DDIM];
    }
    int ch = b * DDIM + d;
    g_pw[j * 8192 + ch] = sw;
    g_pkv[j * 8192 + ch] = skv;
}

__global__ void __launch_bounds__(256) k_scan_ex() {
    int ch = blockIdx.x * 256 + threadIdx.x;     // 0..8191
    float rw = 0.f, rkv = 0.f;
    #pragma unroll
    for (int j = 0; j < 32; ++j) {
        int i = j * 8192 + ch;
        float tw = g_pw[i];  g_pw[i]  = rw;  rw  += tw;
        float tk = g_pkv[i]; g_pkv[i] = rkv; rkv += tk;
    }
}

__global__ void __launch_bounds__(256) k_scan_apply(float* __restrict__ out2) {
    int gid = blockIdx.x * 256 + threadIdx.x;
    int d = gid & (DDIM - 1);
    int rest = gid >> 11;
    int b = rest & 3;
    int j = rest >> 2;
    size_t base = ((size_t)(b * TDIM + j * 128)) * DDIM + d;
    int ch = b * DDIM + d;
    float rw = g_pw[j * 8192 + ch];
    float rkv = g_pkv[j * 8192 + ch];
    #pragma unroll 4
    for (int t = 0; t < 128; ++t) {
        size_t i = base + (size_t)t * DDIM;
        rw  += g_ww[i];
        rkv += g_kv[i];
        float y = rkv / (rw + 1e-6f);
        out2[i] = g_sq[i] * y;
    }
}

// ============================================================================
// Launch
// ============================================================================
extern "C" void kernel_launch(void* const* d_in, const int* in_sizes, int n_in,
                              void* d_out, int out_size) {
    const float* x  = (const float*)d_in[0];   // [4, 4096, 2048]
    const float* wq = (const float*)d_in[1];   // [6144, 2048]
    float* out = (float*)d_out;                // [2, 4, 4096, 2048]

    cudaFuncSetAttribute(k_gemm, cudaFuncAttributeMaxDynamicSharedMemorySize,
                         2 * STAGE_BYTES);

    k_split_w<<<12288, 256>>>(wq);
    k_rms_x<<<MROWS, 256>>>(x, out);
    k_gemm<<<dim3(EDIM / TN, MROWS / TM), GEMM_THREADS, 2 * STAGE_BYTES>>>();
    k_post<<<MROWS, 256>>>();
    k_scan_part<<<1024, 256>>>();
    k_scan_ex<<<32, 256>>>();
    k_scan_apply<<<1024, 256>>>(out + (size_t)MROWS * DDIM);
}

// round 6
// speedup vs baseline: 1.8762x; 1.4318x over previous
#include <cuda_runtime.h>
#include <cuda_bf16.h>
#include <cuda_fp16.h>
#include <cstdint>

// ============================================================================
// Problem constants
// ============================================================================
#define BDIM 4
#define TDIM 4096
#define DDIM 2048
#define MROWS (BDIM * TDIM)        // 16384 rows of x
#define EDIM  (3 * DDIM)           // 6144 output features of qkv
#define KDIM  DDIM                 // 2048 reduction dim
#define EPSF  1.1920929e-07f       // finfo(float32).eps

// GEMM tiling (mma.sync f16, single term xh*wh)
#define TM 128
#define TN 128
#define TK 64                      // K-chunk (64 f16 = 128B rows, SW128)
#define NKC (KDIM / TK)            // 32 chunks
#define GEMM_THREADS 512           // 16 warps: 4 over M x 4 over N, tile 32x32
#define TILE_BYTES  (128 * 128)    // 16KB per [128 x 64 f16] tile
#define STAGE_BYTES (2 * TILE_BYTES)  // A, B = 32KB per stage
#define NSTAGE 3

// ============================================================================
// Scratch (static device globals — allocation-free rule)
// ============================================================================
__device__ __half g_nhi[MROWS * DDIM];          // fp16(rmsnorm(x))
__device__ __half g_whi[EDIM * DDIM];           // fp16(W)
__device__ float g_qkv[(size_t)MROWS * EDIM];   // fp32 qkv
__device__ float g_sq[MROWS * DDIM];            // sigmoid(rmsnorm(q))
__device__ float g_ww[MROWS * DDIM];            // exp(rmsnorm(k))
__device__ float g_kv[MROWS * DDIM];            // w * v
__device__ float g_pw[32 * 8192];               // chunk partials (w)
__device__ float g_pkv[32 * 8192];              // chunk partials (kv)

// ============================================================================
// Helpers
// ============================================================================
__device__ __forceinline__ uint32_t smem_u32(const void* p) {
    uint32_t a;
    asm("{ .reg .u64 t; cvta.to.shared.u64 t, %1; cvt.u32.u64 %0, t; }" : "=r"(a) : "l"(p));
    return a;
}

#define SMEM_SWIZZLE_128B(off) ((off) ^ (((off) >> 3) & 0x70))

__device__ __forceinline__ void cp_async16(uint32_t dst, const void* src) {
    asm volatile("cp.async.cg.shared.global [%0], [%1], 16;" :: "r"(dst), "l"(src));
}
__device__ __forceinline__ void cp_commit() {
    asm volatile("cp.async.commit_group;" ::: "memory");
}
__device__ __forceinline__ void cp_wait2() {
    asm volatile("cp.async.wait_group 2;" ::: "memory");
}
__device__ __forceinline__ void cp_wait1() {
    asm volatile("cp.async.wait_group 1;" ::: "memory");
}
__device__ __forceinline__ void cp_wait0() {
    asm volatile("cp.async.wait_group 0;" ::: "memory");
}

__device__ __forceinline__ void ldmx4(uint32_t* r, uint32_t addr) {
    asm volatile("ldmatrix.sync.aligned.m8n8.x4.shared.b16 {%0,%1,%2,%3}, [%4];"
                 : "=r"(r[0]), "=r"(r[1]), "=r"(r[2]), "=r"(r[3]) : "r"(addr));
}

__device__ __forceinline__ void mma16816(float* c, const uint32_t* a, const uint32_t* b) {
    asm volatile(
        "mma.sync.aligned.m16n8k16.row.col.f32.f16.f16.f32 "
        "{%0,%1,%2,%3}, {%4,%5,%6,%7}, {%8,%9}, {%0,%1,%2,%3};"
        : "+f"(c[0]), "+f"(c[1]), "+f"(c[2]), "+f"(c[3])
        : "r"(a[0]), "r"(a[1]), "r"(a[2]), "r"(a[3]), "r"(b[0]), "r"(b[1]));
}

// ============================================================================
// Block reduce (two values at once; safe for repeated calls)
// ============================================================================
__device__ __forceinline__ void blockReduce2(float& a, float& b) {
    __shared__ float sa[8], sb[8];
    int tid = threadIdx.x, wid = tid >> 5, lid = tid & 31;
    #pragma unroll
    for (int o = 16; o > 0; o >>= 1) {
        a += __shfl_xor_sync(0xffffffffu, a, o);
        b += __shfl_xor_sync(0xffffffffu, b, o);
    }
    if (lid == 0) { sa[wid] = a; sb[wid] = b; }
    __syncthreads();
    if (tid < 32) {
        a = (lid < 8) ? sa[lid] : 0.f;
        b = (lid < 8) ? sb[lid] : 0.f;
        #pragma unroll
        for (int o = 4; o > 0; o >>= 1) {
            a += __shfl_xor_sync(0xffffffffu, a, o);
            b += __shfl_xor_sync(0xffffffffu, b, o);
        }
        if (lid == 0) { sa[0] = a; sb[0] = b; }
    }
    __syncthreads();
    a = sa[0]; b = sb[0];
    __syncthreads();
}

// ============================================================================
// Kernel 0: W -> fp16
// ============================================================================
__global__ void __launch_bounds__(256) k_split_w(const float* __restrict__ w) {
    int idx = blockIdx.x * 256 + threadIdx.x;
    const int n = EDIM * DDIM;
    #pragma unroll 4
    for (int i = idx; i < n; i += gridDim.x * 256) {
        g_whi[i] = __float2half_rn(w[i]);
    }
}

// ============================================================================
// Kernel 1: rmsnorm(x) -> fp16; also copy x into out[0]
// ============================================================================
__global__ void __launch_bounds__(256) k_rms_x(const float* __restrict__ x,
                                               float* __restrict__ outx) {
    int row = blockIdx.x, tid = threadIdx.x;
    const float* xr = x + (size_t)row * DDIM;
    float v[8];
    float s = 0.f, dummy = 0.f;
    #pragma unroll
    for (int i = 0; i < 8; ++i) {
        v[i] = xr[i * 256 + tid];
        s += v[i] * v[i];
    }
    blockReduce2(s, dummy);
    float r = rsqrtf(s * (1.0f / DDIM) + EPSF);
    size_t ob = (size_t)row * DDIM;
    #pragma unroll
    for (int i = 0; i < 8; ++i) {
        int c = i * 256 + tid;
        outx[ob + c] = v[i];
        g_nhi[ob + c] = __float2half_rn(v[i] * r);
    }
}

// ============================================================================
// Kernel 2: QKV GEMM via mma.sync fp16 (single term)
// C[m, e] = sum_d N[m, d] * W[e, d]   (both K-major -> D = A @ B^T)
// CTA tile 128x128, K-chunk 64, 3-stage cp.async, 16 warps (4M x 4N),
// warp tile 32x32. SW128-swizzled SMEM -> conflict-free ldmatrix + cp.async.
// ============================================================================
__device__ __forceinline__ void gemm_load_chunk(uint32_t sb_stage, int m0, int n0,
                                                int kc, int tid) {
    const int k0 = kc * TK;
    const int v = tid & 7;                              // 16B vector 0..7
    #pragma unroll
    for (int i = 0; i < 4; ++i) {
        const int tile = i >> 1;                        // 0:A 1:B
        const int r = (i & 1) * 64 + (tid >> 3);        // row 0..127
        uint32_t dst = sb_stage + tile * TILE_BYTES +
                       SMEM_SWIZZLE_128B((uint32_t)(r * 128 + v * 16));
        const __half* src = (tile == 0)
            ? g_nhi + (size_t)(m0 + r) * KDIM + k0 + v * 8
            : g_whi + (size_t)(n0 + r) * KDIM + k0 + v * 8;
        cp_async16(dst, src);
    }
}

__global__ void __launch_bounds__(GEMM_THREADS, 1) k_gemm() {
    extern __shared__ char smem[];
    const uint32_t sb = smem_u32(smem);
    const int tid = threadIdx.x;
    const int wid = tid >> 5, lane = tid & 31;
    const int warpM = wid & 3;          // 4 warps over M
    const int warpN = wid >> 2;         // 4 warps over N
    const int n0 = blockIdx.x * TN;
    const int m0 = blockIdx.y * TM;

    float c[2][4][4];
    #pragma unroll
    for (int mt = 0; mt < 2; ++mt)
        #pragma unroll
        for (int nt = 0; nt < 4; ++nt)
            #pragma unroll
            for (int j = 0; j < 4; ++j) c[mt][nt][j] = 0.f;

    gemm_load_chunk(sb + 0 * STAGE_BYTES, m0, n0, 0, tid);
    cp_commit();
    gemm_load_chunk(sb + 1 * STAGE_BYTES, m0, n0, 1, tid);
    cp_commit();

    // Precomputed per-lane smem sub-offsets
    const int aRow = warpM * 32 + (lane & 15);
    const int aKb  = (lane >> 4) << 4;
    const int bRow = warpN * 32 + (lane & 7) + ((lane & 16) >> 1);
    const int bKb  = ((lane >> 3) & 1) << 4;

    int stage = 0;
    for (int kc = 0; kc < NKC; ++kc) {
        if (kc + 2 < NKC) {
            int ls = (stage + 2); if (ls >= NSTAGE) ls -= NSTAGE;
            gemm_load_chunk(sb + ls * STAGE_BYTES, m0, n0, kc + 2, tid);
            cp_commit();
            cp_wait2();
        } else if (kc + 1 < NKC) {
            cp_wait1();
        } else {
            cp_wait0();
        }
        __syncthreads();

        const uint32_t st = sb + stage * STAGE_BYTES;
        #pragma unroll
        for (int ks = 0; ks < 4; ++ks) {
            uint32_t ah[2][4], bh[4][2];
            #pragma unroll
            for (int mt = 0; mt < 2; ++mt) {
                uint32_t off = SMEM_SWIZZLE_128B(
                    (uint32_t)((aRow + mt * 16) * 128 + ks * 32 + aKb));
                ldmx4(ah[mt], st + 0 * TILE_BYTES + off);
            }
            #pragma unroll
            for (int pt = 0; pt < 2; ++pt) {
                uint32_t off = SMEM_SWIZZLE_128B(
                    (uint32_t)((bRow + pt * 16) * 128 + ks * 32 + bKb));
                uint32_t rh[4];
                ldmx4(rh, st + 1 * TILE_BYTES + off);
                bh[2 * pt][0] = rh[0]; bh[2 * pt][1] = rh[1];
                bh[2 * pt + 1][0] = rh[2]; bh[2 * pt + 1][1] = rh[3];
            }
            #pragma unroll
            for (int mt = 0; mt < 2; ++mt)
                #pragma unroll
                for (int nt = 0; nt < 4; ++nt)
                    mma16816(c[mt][nt], ah[mt], bh[nt]);
        }
        __syncthreads();
        if (++stage == NSTAGE) stage = 0;
    }

    // Epilogue: write fp32 qkv
    const int m_base = m0 + warpM * 32;
    const int n_base = n0 + warpN * 32;
    #pragma unroll
    for (int mt = 0; mt < 2; ++mt)
        #pragma unroll
        for (int nt = 0; nt < 4; ++nt) {
            int r0 = m_base + mt * 16 + (lane >> 2);
            int cc = n_base + nt * 8 + (lane & 3) * 2;
            float2 v0 = make_float2(c[mt][nt][0], c[mt][nt][1]);
            float2 v1 = make_float2(c[mt][nt][2], c[mt][nt][3]);
            *(float2*)(g_qkv + (size_t)r0 * EDIM + cc) = v0;
            *(float2*)(g_qkv + (size_t)(r0 + 8) * EDIM + cc) = v1;
        }
}

// ============================================================================
// Kernel 3: rmsnorm(q), rmsnorm(k), sigmoid(q), w=exp(k), kv=w*v
// ============================================================================
__global__ void __launch_bounds__(256) k_post() {
    int row = blockIdx.x, tid = threadIdx.x;
    const float* q = g_qkv + (size_t)row * EDIM;
    float qv[8], kk[8], vv[8];
    float sq = 0.f, sk = 0.f;
    #pragma unroll
    for (int i = 0; i < 8; ++i) {
        int c = i * 256 + tid;
        qv[i] = q[c];
        kk[i] = q[c + DDIM];
        vv[i] = q[c + 2 * DDIM];
        sq += qv[i] * qv[i];
        sk += kk[i] * kk[i];
    }
    blockReduce2(sq, sk);
    float rq = rsqrtf(sq * (1.0f / DDIM) + EPSF);
    float rk = rsqrtf(sk * (1.0f / DDIM) + EPSF);
    size_t ob = (size_t)row * DDIM;
    #pragma unroll
    for (int i = 0; i < 8; ++i) {
        int c = i * 256 + tid;
        float qn = qv[i] * rq;
        g_sq[ob + c] = 1.0f / (1.0f + expf(-qn));
        float w = expf(kk[i] * rk);
        g_ww[ob + c] = w;
        g_kv[ob + c] = w * vv[i];
    }
}

// ============================================================================
// Kernel 4a/4b/4c: chunked cumsum over T per (b, d) channel, then output
// ============================================================================
__global__ void __launch_bounds__(256) k_scan_part() {
    int gid = blockIdx.x * 256 + threadIdx.x;    // 0..262143
    int d = gid & (DDIM - 1);
    int rest = gid >> 11;
    int b = rest & 3;
    int j = rest >> 2;                           // chunk 0..31
    size_t base = ((size_t)(b * TDIM + j * 128)) * DDIM + d;
    float sw = 0.f, skv = 0.f;
    #pragma unroll 4
    for (int t = 0; t < 128; ++t) {
        sw  += g_ww[base + (size_t)t * DDIM];
        skv += g_kv[base + (size_t)t * DDIM];
    }
    int ch = b * DDIM + d;
    g_pw[j * 8192 + ch] = sw;
    g_pkv[j * 8192 + ch] = skv;
}

__global__ void __launch_bounds__(256) k_scan_ex() {
    int ch = blockIdx.x * 256 + threadIdx.x;     // 0..8191
    float rw = 0.f, rkv = 0.f;
    #pragma unroll
    for (int j = 0; j < 32; ++j) {
        int i = j * 8192 + ch;
        float tw = g_pw[i];  g_pw[i]  = rw;  rw  += tw;
        float tk = g_pkv[i]; g_pkv[i] = rkv; rkv += tk;
    }
}

__global__ void __launch_bounds__(256) k_scan_apply(float* __restrict__ out2) {
    int gid = blockIdx.x * 256 + threadIdx.x;
    int d = gid & (DDIM - 1);
    int rest = gid >> 11;
    int b = rest & 3;
    int j = rest >> 2;
    size_t base = ((size_t)(b * TDIM + j * 128)) * DDIM + d;
    int ch = b * DDIM + d;
    float rw = g_pw[j * 8192 + ch];
    float rkv = g_pkv[j * 8192 + ch];
    #pragma unroll 4
    for (int t = 0; t < 128; ++t) {
        size_t i = base + (size_t)t * DDIM;
        rw  += g_ww[i];
        rkv += g_kv[i];
        float y = rkv / (rw + 1e-6f);
        out2[i] = g_sq[i] * y;
    }
}

// ============================================================================
// Launch
// ============================================================================
extern "C" void kernel_launch(void* const* d_in, const int* in_sizes, int n_in,
                              void* d_out, int out_size) {
    const float* x  = (const float*)d_in[0];   // [4, 4096, 2048]
    const float* wq = (const float*)d_in[1];   // [6144, 2048]
    float* out = (float*)d_out;                // [2, 4, 4096, 2048]

    cudaFuncSetAttribute(k_gemm, cudaFuncAttributeMaxDynamicSharedMemorySize,
                         NSTAGE * STAGE_BYTES);

    k_split_w<<<12288, 256>>>(wq);
    k_rms_x<<<MROWS, 256>>>(x, out);
    k_gemm<<<dim3(EDIM / TN, MROWS / TM), GEMM_THREADS, NSTAGE * STAGE_BYTES>>>();
    k_post<<<MROWS, 256>>>();
    k_scan_part<<<1024, 256>>>();
    k_scan_ex<<<32, 256>>>();
    k_scan_apply<<<1024, 256>>>(out + (size_t)MROWS * DDIM);
}